// round 17
// baseline (speedup 1.0000x reference)
#include <cuda_runtime.h>
#include <cuda_fp16.h>
#include <mma.h>
#include <math.h>

using namespace nvcuda;

#define NPTS 65536
#define CDIM 256
#define KWIN 32
#define NWIN 2048
#define LXYZ 40
#define LRGB 32
#define QSF 4.0f
#define CQSF 8.0f
#define QK_SCALE 0.25f

// value-table (transposed [row][c][h][8]) offsets in g_tabh (halfs)
#define T_VX 0
#define T_VR 30720
#define T_VTOT 55296

// combined logit tables [h][c][224] (l 0..215 valid, 216..223 zero)
#define CT_H_STRIDE 3584          // 16c * 224l
#define P_STRIDE 3584             // 224 l * 16 h halfs per point

// Scratch (allocation-free rule: device globals; zero-initialized)
__device__ float g_qkv[(size_t)NPTS * 768];
__device__ __align__(16) __half g_midh[(size_t)NPTS * CDIM];
__device__ __align__(16) __half g_tabh[T_VTOT];
__device__ __align__(16) __half g_ctk[16 * CT_H_STRIDE];
__device__ __align__(16) __half g_ctq[16 * CT_H_STRIDE];
__device__ __align__(16) __half g_pq[(size_t)NPTS * P_STRIDE];
__device__ __align__(16) __half g_pk[(size_t)NPTS * P_STRIDE];
__device__ __align__(16) __half g_ah[(size_t)NPTS * 256];
__device__ __align__(16) __half g_w1h[768 * 256];
__device__ __align__(16) __half g_w2h[256 * 256];

// ---------------------------------------------------------------------------
// Table conversion: value tables (transposed fp16) + logit tables [h][c][l]
// ---------------------------------------------------------------------------
__global__ void cvt_tabs(const float* __restrict__ kx, const float* __restrict__ qx,
                         const float* __restrict__ vx, const float* __restrict__ kr,
                         const float* __restrict__ qr, const float* __restrict__ vr)
{
    int i = blockIdx.x * 256 + threadIdx.x;
    // value transposed dst: [row][c8][h][8]
    int vdst = (i & ~255) | ((i & 8) << 4) | ((i & 240) >> 1) | (i & 7);
    if (i < 30720) {                       // xyz: row = i>>8 in [0,120)
        int row = i >> 8, hh = (i >> 4) & 15, cc = i & 15;
        g_ctk[hh * CT_H_STRIDE + cc * 224 + row] = __float2half(kx[i]);
        g_ctq[hh * CT_H_STRIDE + cc * 224 + row] = __float2half(qx[i]);
        g_tabh[T_VX + vdst] = __float2half(vx[i]);
    }
    if (i < 24576) {                       // rgb: row = 120 + (i>>8)
        int row = 120 + (i >> 8), hh = (i >> 4) & 15, cc = i & 15;
        g_ctk[hh * CT_H_STRIDE + cc * 224 + row] = __float2half(kr[i]);
        g_ctq[hh * CT_H_STRIDE + cc * 224 + row] = __float2half(qr[i]);
        g_tabh[T_VR + vdst] = __float2half(vr[i]);
    }
}

// grid-stride fp32 -> fp16 GEMM operands
__global__ void cvt_ops(const float* __restrict__ feats,
                        const float* __restrict__ w1, const float* __restrict__ w2)
{
    const int NA = NPTS * 256 / 2, N1 = 768 * 256 / 2, N2 = 256 * 256 / 2;
    for (int i = blockIdx.x * blockDim.x + threadIdx.x; i < NA;
         i += gridDim.x * blockDim.x) {
        ((__half2*)g_ah)[i] = __float22half2_rn(((const float2*)feats)[i]);
        if (i < N1) ((__half2*)g_w1h)[i] = __float22half2_rn(((const float2*)w1)[i]);
        if (i < N2) ((__half2*)g_w2h)[i] = __float22half2_rn(((const float2*)w2)[i]);
    }
}

// ---------------------------------------------------------------------------
// Precompute PQ[p][l][h] = (q_p*scale).ktab[l][h], PK[p][l][h] = k_p.qtab[l][h]
// via m16n16k16 HMMA (fp32 acc). CTA = 16 points; warps parallel over h.
// Output layout [pt][l][h] via smem transpose -> coalesced 32B rows.
// ---------------------------------------------------------------------------
__global__ __launch_bounds__(256, 4) void precompute_P()
{
    __shared__ __align__(16) __half sqk[2][16 * 256];   // [side][pt][c]
    __shared__ __align__(16) float scr[8][256];         // per-warp C tile
    __shared__ __align__(16) __half stage[256 * 18];    // [(pt*16+l)][18] (h 0..15)
    const int tid = threadIdx.x, wid = tid >> 5, lane = tid & 31;
    const int p0 = blockIdx.x * 16;

    for (int e = tid; e < 16 * 256; e += 256) {
        int pt = e >> 8, c = e & 255;
        size_t base = (size_t)(p0 + pt) * 768;
        sqk[0][e] = __float2half(g_qkv[base + c] * QK_SCALE);
        sqk[1][e] = __float2half(g_qkv[base + 256 + c]);
    }
    __syncthreads();

    for (int side = 0; side < 2; side++) {
        const __half* ct = side ? g_ctq : g_ctk;
        __half* dst = side ? g_pk : g_pq;
        for (int lt = 0; lt < 14; lt++) {
#pragma unroll
            for (int hh = wid; hh < 16; hh += 8) {
                wmma::fragment<wmma::matrix_a, 16, 16, 16, __half, wmma::row_major> a;
                wmma::fragment<wmma::matrix_b, 16, 16, 16, __half, wmma::row_major> b;
                wmma::fragment<wmma::accumulator, 16, 16, 16, float> c;
                wmma::fill_fragment(c, 0.f);
                wmma::load_matrix_sync(a, &sqk[side][hh * 16], 256);
                wmma::load_matrix_sync(b, ct + hh * CT_H_STRIDE + lt * 16, 224);
                wmma::mma_sync(c, a, b, c);
                wmma::store_matrix_sync(scr[wid], c, 16, wmma::mem_row_major);
                __syncwarp();
                for (int e = lane; e < 256; e += 32)
                    stage[e * 18 + hh] = __float2half(scr[wid][e]);
                __syncwarp();
            }
            __syncthreads();
            {   // write stage -> dst[(p0+pt)*P_STRIDE + (lt*16+l)*16 + h]
                int pt = tid >> 4, l = tid & 15;
                const unsigned* s = (const unsigned*)(stage + tid * 18);
                unsigned v0 = s[0], v1 = s[1], v2 = s[2], v3 = s[3];
                unsigned v4 = s[4], v5 = s[5], v6 = s[6], v7 = s[7];
                uint4* d = (uint4*)&dst[(size_t)(p0 + pt) * P_STRIDE +
                                        (lt * 16 + l) * 16];
                d[0] = make_uint4(v0, v1, v2, v3);
                d[1] = make_uint4(v4, v5, v6, v7);
            }
            __syncthreads();
        }
    }
}

// ---------------------------------------------------------------------------
// fp16 tensor-core GEMM (fp32 accumulate), fp16 operands (r16, unchanged)
// ---------------------------------------------------------------------------
#define HS 40

__global__ __launch_bounds__(256, 2) void gemm_fp16(
    const __half* __restrict__ A, const __half* __restrict__ Wm,
    const float* __restrict__ bias, float* __restrict__ Cm,
    int M, int N, int Kd)
{
    __shared__ __align__(16) __half As[2][128 * HS];
    __shared__ __align__(16) __half Bs[2][128 * HS];
    __shared__ __align__(16) float scratch[8][256];

    const int tid = threadIdx.x;
    const int wid = tid >> 5;
    const int lane = tid & 31;
    const int brow = blockIdx.y * 128;
    const int bcol = blockIdx.x * 128;
    const int m0 = (wid >> 1) * 32;
    const int n0 = (wid & 1) * 64;

    const int lrow = tid >> 1;
    const int lcb = (tid & 1) * 16;
    const __half* Ap = A + (size_t)(brow + lrow) * Kd + lcb;
    const __half* Wp = Wm + (size_t)(bcol + lrow) * Kd + lcb;

    wmma::fragment<wmma::accumulator, 16, 16, 16, float> acc[2][4];
#pragma unroll
    for (int mi = 0; mi < 2; mi++)
#pragma unroll
        for (int ni = 0; ni < 4; ni++) wmma::fill_fragment(acc[mi][ni], 0.f);

    {
        uint4 a0 = *(const uint4*)Ap, a1 = *(const uint4*)(Ap + 8);
        uint4 w0 = *(const uint4*)Wp, w1 = *(const uint4*)(Wp + 8);
        *(uint4*)&As[0][lrow * HS + lcb] = a0;
        *(uint4*)&As[0][lrow * HS + lcb + 8] = a1;
        *(uint4*)&Bs[0][lrow * HS + lcb] = w0;
        *(uint4*)&Bs[0][lrow * HS + lcb + 8] = w1;
    }
    __syncthreads();

    const int nT = Kd / 32;
    for (int kt = 0; kt < nT; kt++) {
        const int buf = kt & 1;
        uint4 a0, a1, w0, w1;
        const bool more = (kt + 1 < nT);
        if (more) {
            const __half* Ax = Ap + (kt + 1) * 32;
            const __half* Wx = Wp + (kt + 1) * 32;
            a0 = *(const uint4*)Ax; a1 = *(const uint4*)(Ax + 8);
            w0 = *(const uint4*)Wx; w1 = *(const uint4*)(Wx + 8);
        }
#pragma unroll
        for (int ks = 0; ks < 2; ks++) {
            wmma::fragment<wmma::matrix_a, 16, 16, 16, __half, wmma::row_major> af[2];
            wmma::fragment<wmma::matrix_b, 16, 16, 16, __half, wmma::col_major> bf[4];
#pragma unroll
            for (int mi = 0; mi < 2; mi++)
                wmma::load_matrix_sync(af[mi],
                    &As[buf][(m0 + 16 * mi) * HS + ks * 16], HS);
#pragma unroll
            for (int ni = 0; ni < 4; ni++)
                wmma::load_matrix_sync(bf[ni],
                    &Bs[buf][(n0 + 16 * ni) * HS + ks * 16], HS);
#pragma unroll
            for (int mi = 0; mi < 2; mi++)
#pragma unroll
                for (int ni = 0; ni < 4; ni++)
                    wmma::mma_sync(acc[mi][ni], af[mi], bf[ni], acc[mi][ni]);
        }
        if (more) {
            const int b2 = buf ^ 1;
            *(uint4*)&As[b2][lrow * HS + lcb] = a0;
            *(uint4*)&As[b2][lrow * HS + lcb + 8] = a1;
            *(uint4*)&Bs[b2][lrow * HS + lcb] = w0;
            *(uint4*)&Bs[b2][lrow * HS + lcb + 8] = w1;
        }
        __syncthreads();
    }

#pragma unroll
    for (int mi = 0; mi < 2; mi++) {
#pragma unroll
        for (int ni = 0; ni < 4; ni++) {
            wmma::store_matrix_sync(scratch[wid], acc[mi][ni], 16,
                                    wmma::mem_row_major);
            __syncwarp();
#pragma unroll
            for (int e = 0; e < 8; e++) {
                int id = e * 32 + lane;
                int rr = id >> 4, cc = id & 15;
                int col = bcol + n0 + 16 * ni + cc;
                Cm[(size_t)(brow + m0 + 16 * mi + rr) * N + col] =
                    scratch[wid][rr * 16 + cc] + __ldg(&bias[col]);
            }
            __syncwarp();
        }
    }
}

// ---------------------------------------------------------------------------
// Windowed attention: logit tables via PQ/PK scalar lookups; value side = r13.
// ---------------------------------------------------------------------------
struct H8 { uint4 u; };
__device__ __forceinline__ H8 ldt(const __half* __restrict__ p) {
    H8 r; r.u = *(const uint4*)p; return r;
}
__device__ __forceinline__ __half2 lane(const H8& a, int l) {
    unsigned w = (l == 0) ? a.u.x : (l == 1) ? a.u.y : (l == 2) ? a.u.z : a.u.w;
    return *reinterpret_cast<const __half2*>(&w);
}
__device__ __forceinline__ __half2 sum6(const H8& a0, const H8& a1, const H8& a2,
                                        const H8& a3, const H8& a4, const H8& a5, int l) {
    return __hadd2(__hadd2(__hadd2(lane(a0, l), lane(a1, l)),
                           __hadd2(lane(a2, l), lane(a3, l))),
                   __hadd2(lane(a4, l), lane(a5, l)));
}

// smem layout (float offsets):
//   sk     [32*320] fp32 @ 0..10240   (h-stride 20, conflict-free)
//   sv     [32*320] fp32 @ 10240..20480
//   scoord [192]         @ 20480
//   spt    [32] int      @ 20672
//   sidx2  [1024] uint2  @ 20704..22752
#define ATTN_SMEM_FLOATS 22752
#define ATTN_SMEM_BYTES (ATTN_SMEM_FLOATS * 4)

__global__ __launch_bounds__(256, 2) void win_attn(
    const float* __restrict__ n_coords, const int* __restrict__ n2n)
{
    extern __shared__ float smem[];
    float* sk = smem;
    float* sv = smem + 10240;
    float* scoord = smem + 20480;
    int* spt = (int*)(smem + 20672);
    uint2* sidx2 = (uint2*)(smem + 20704);

    const int tid = threadIdx.x;
    const int w = blockIdx.x;

    if (tid < KWIN) spt[tid] = n2n[w * KWIN + tid];
    __syncthreads();

    if (tid < 192) {
        int i = tid / 6, d = tid % 6;
        float s = (d < 3) ? QSF : CQSF;
        scoord[tid] = n_coords[(size_t)spt[i] * 6 + d] * s;
    }
    {
        const int h = tid >> 4, c = tid & 15;
        for (int j = 0; j < KWIN; ++j) {
            size_t base = (size_t)spt[j] * 768;
            sk[j * 320 + h * 20 + c] = g_qkv[base + 256 + tid];
            sv[j * 320 + h * 20 + c] = g_qkv[base + 512 + tid];
        }
    }
    __syncthreads();

#pragma unroll
    for (int r = 0; r < 4; ++r) {
        int p = r * 256 + tid;
        int i = p >> 5, j = p & 31;
        const float* ci = scoord + i * 6;
        const float* cj = scoord + j * 6;
        int l[6];
#pragma unroll
        for (int d = 0; d < 3; d++) {
            int v = (int)floorf(ci[d] - cj[d]) + LXYZ / 2;
            l[d] = min(max(v, 0), LXYZ - 1);
        }
#pragma unroll
        for (int d = 0; d < 3; d++) {
            int v = (int)floorf(ci[3 + d] - cj[3 + d]) + LRGB / 2;
            l[3 + d] = min(max(v, 0), LRGB - 1);
        }
        unsigned lo = (unsigned)l[0] | ((unsigned)l[1] << 8) |
                      ((unsigned)l[2] << 16) | ((unsigned)l[3] << 24);
        unsigned hi = (unsigned)l[4] | ((unsigned)l[5] << 8);
        sidx2[p] = make_uint2(lo, hi);
    }
    __syncthreads();

    for (int r = 0; r < 2; ++r) {
        const int row = r * 256 + tid;
        const int i = row >> 4;
        const int h = row & 15;
        const int hb = h * 16;
        const int pt = spt[i];

        const __half* tVX = g_tabh + T_VX + h * 8;
        const __half* tVR = g_tabh + T_VR + h * 8;
        const __half* pqi = g_pq + (size_t)pt * P_STRIDE + h;

        // q row (scaled) fp32
        float qf[16];
        {
            const float4* qp = (const float4*)(g_qkv + (size_t)pt * 768 + hb);
#pragma unroll
            for (int t = 0; t < 4; t++) {
                float4 v = qp[t];
                qf[t * 4 + 0] = v.x * QK_SCALE; qf[t * 4 + 1] = v.y * QK_SCALE;
                qf[t * 4 + 2] = v.z * QK_SCALE; qf[t * 4 + 3] = v.w * QK_SCALE;
            }
        }

        // softmax baseline from j=0 main dot
        float bshift = 0.f;
        {
            const float* k0 = sk + h * 20;
#pragma unroll
            for (int t = 0; t < 4; t++) {
                float4 kv = *(const float4*)(k0 + 4 * t);
                bshift += qf[4 * t + 0] * kv.x + qf[4 * t + 1] * kv.y +
                          qf[4 * t + 2] * kv.z + qf[4 * t + 3] * kv.w;
            }
        }

        float ssum = 0.f;
        float of[16];
#pragma unroll
        for (int e = 0; e < 16; e++) of[e] = 0.f;

        for (int j = 0; j < KWIN; ++j) {
            const uint2 pk = sidx2[i * 32 + j];
            const int i0 = (int)(pk.x & 255), i1 = (int)((pk.x >> 8) & 255),
                      i2 = (int)((pk.x >> 16) & 255), i3 = (int)(pk.x >> 24),
                      i4 = (int)(pk.y & 255), i5 = (int)((pk.y >> 8) & 255);

            // fp32 main q.k dot
            const float* kj = sk + j * 320 + h * 20;
            float facc = 0.f;
#pragma unroll
            for (int t = 0; t < 4; t++) {
                float4 kv = *(const float4*)(kj + 4 * t);
                facc += qf[4 * t + 0] * kv.x + qf[4 * t + 1] * kv.y +
                        qf[4 * t + 2] * kv.z + qf[4 * t + 3] * kv.w;
            }

            // precomputed logit tables: 12 scalar fp16 lookups
            {
                const __half* pkj = g_pk + (size_t)spt[j] * P_STRIDE + h;
                const int pA = i0 << 4, pB = (40 + i1) << 4, pC = (80 + i2) << 4,
                          pD = (120 + i3) << 4, pE = (152 + i4) << 4,
                          pF = (184 + i5) << 4;
                facc += __half2float(__ldg(pqi + pA)) + __half2float(__ldg(pqi + pB)) +
                        __half2float(__ldg(pqi + pC)) + __half2float(__ldg(pqi + pD)) +
                        __half2float(__ldg(pqi + pE)) + __half2float(__ldg(pqi + pF)) +
                        __half2float(__ldg(pkj + pA)) + __half2float(__ldg(pkj + pB)) +
                        __half2float(__ldg(pkj + pC)) + __half2float(__ldg(pkj + pD)) +
                        __half2float(__ldg(pkj + pE)) + __half2float(__ldg(pkj + pF));
            }

            const float a = __expf(facc - bshift);
            ssum += a;

            // value side: a * (v + 6 gathered value-table rows)
            const int r0 = i0 << 8, r1 = (40 + i1) << 8, r2 = (80 + i2) << 8;
            const int r3 = i3 << 8, r4 = (32 + i4) << 8, r5 = (64 + i5) << 8;
            const float* vj = sv + j * 320 + h * 20;
#pragma unroll
            for (int c = 0; c < 2; c++) {
                const int co = c << 7;
                H8 v0 = ldt(tVX + r0 + co), v1 = ldt(tVX + r1 + co),
                   v2 = ldt(tVX + r2 + co), v3 = ldt(tVR + r3 + co),
                   v4 = ldt(tVR + r4 + co), v5 = ldt(tVR + r5 + co);
                float4 va = *(const float4*)(vj + 8 * c);
                float4 vb = *(const float4*)(vj + 8 * c + 4);
                float2 t0 = __half22float2(sum6(v0, v1, v2, v3, v4, v5, 0));
                float2 t1 = __half22float2(sum6(v0, v1, v2, v3, v4, v5, 1));
                float2 t2 = __half22float2(sum6(v0, v1, v2, v3, v4, v5, 2));
                float2 t3 = __half22float2(sum6(v0, v1, v2, v3, v4, v5, 3));
                float* o = of + c * 8;
                o[0] += a * (va.x + t0.x); o[1] += a * (va.y + t0.y);
                o[2] += a * (va.z + t1.x); o[3] += a * (va.w + t1.y);
                o[4] += a * (vb.x + t2.x); o[5] += a * (vb.y + t2.y);
                o[6] += a * (vb.z + t3.x); o[7] += a * (vb.w + t3.y);
            }
        }

        const float inv = 1.0f / ssum;
        __half2* op = (__half2*)(g_midh + (size_t)pt * CDIM + hb);
#pragma unroll
        for (int k = 0; k < 8; k++)
            op[k] = __floats2half2_rn(of[2 * k] * inv, of[2 * k + 1] * inv);
    }
}

// ---------------------------------------------------------------------------
extern "C" void kernel_launch(void* const* d_in, const int* in_sizes, int n_in,
                              void* d_out, int out_size)
{
    const float* feats    = (const float*)d_in[0];
    const float* n_coords = (const float*)d_in[1];
    const int*   n2n      = (const int*)d_in[2];
    const float* q_xyz    = (const float*)d_in[3];
    const float* k_xyz    = (const float*)d_in[4];
    const float* v_xyz    = (const float*)d_in[5];
    const float* q_rgb    = (const float*)d_in[6];
    const float* k_rgb    = (const float*)d_in[7];
    const float* v_rgb    = (const float*)d_in[8];
    const float* qkv_w    = (const float*)d_in[9];
    const float* qkv_b    = (const float*)d_in[10];
    const float* proj_w   = (const float*)d_in[11];
    const float* proj_b   = (const float*)d_in[12];
    float* out = (float*)d_out;

    float* qkv_p = nullptr;
    __half *ah_p = nullptr, *w1_p = nullptr, *w2_p = nullptr, *midh_p = nullptr;
    cudaGetSymbolAddress((void**)&qkv_p, g_qkv);
    cudaGetSymbolAddress((void**)&ah_p, g_ah);
    cudaGetSymbolAddress((void**)&w1_p, g_w1h);
    cudaGetSymbolAddress((void**)&w2_p, g_w2h);
    cudaGetSymbolAddress((void**)&midh_p, g_midh);

    cudaFuncSetAttribute(win_attn, cudaFuncAttributeMaxDynamicSharedMemorySize,
                         ATTN_SMEM_BYTES);

    // 1) prep conversions
    cvt_tabs<<<120, 256>>>(k_xyz, q_xyz, v_xyz, k_rgb, q_rgb, v_rgb);
    cvt_ops<<<2048, 256>>>(feats, qkv_w, proj_w);

    // 2) QKV projection (fp16 operands)
    dim3 g1(768 / 128, NPTS / 128);
    gemm_fp16<<<g1, 256>>>(ah_p, w1_p, qkv_b, qkv_p, NPTS, 768, CDIM);

    // 3) logit-table precompute (tensor cores) — profiled at slot #4
    precompute_P<<<NPTS / 16, 256>>>();

    // 4) windowed attention
    win_attn<<<NWIN, 256, ATTN_SMEM_BYTES>>>(n_coords, n2n);

    // 5) output projection
    dim3 g2(CDIM / 128, NPTS / 128);
    gemm_fp16<<<g2, 256>>>(midh_p, w2_p, proj_b, out, NPTS, CDIM, CDIM);
}